// round 15
// baseline (speedup 1.0000x reference)
#include <cuda_runtime.h>
#include <cuda_bf16.h>
#include <stdint.h>

#define SS 128
#define LL 384
#define DD 256
#define HH 8
#define HD 32
#define SCALE 0.17677669529663687f

#define NROWS (SS * LL)            // 49152
#define NP_A  (NROWS * DD / 2)     // packed bf16x2 count
#define NP_W  (DD * DD / 2)

// ---- scratch (static device globals) ---------------------------------------
__device__ __align__(16) uint32_t g_ahi[NP_A];
__device__ __align__(16) uint32_t g_alo[NP_A];
__device__ __align__(16) uint32_t g_whi[4 * NP_W];
__device__ __align__(16) uint32_t g_wlo[4 * NP_W];
__device__ __align__(16) uint32_t g_qb[NP_A];
__device__ __align__(16) uint32_t g_kb[NP_A];
__device__ __align__(16) uint32_t g_vh[NP_A];
__device__ __align__(16) uint32_t g_vl[NP_A];
__device__ __align__(16) uint32_t g_oh[NP_A];
__device__ __align__(16) uint32_t g_ol[NP_A];

// ============================================================================
// helpers
// ============================================================================
__device__ __forceinline__ uint32_t smem_u32(const void* p) {
    uint32_t a;
    asm("{ .reg .u64 t; cvta.to.shared.u64 t, %1; cvt.u32.u64 %0, t; }"
        : "=r"(a) : "l"(p));
    return a;
}
__device__ __forceinline__ void ldm_x4(uint32_t* r, uint32_t addr) {
    asm volatile("ldmatrix.sync.aligned.m8n8.x4.shared.b16 {%0,%1,%2,%3}, [%4];"
                 : "=r"(r[0]), "=r"(r[1]), "=r"(r[2]), "=r"(r[3]) : "r"(addr));
}
__device__ __forceinline__ void ldm_x4_t(uint32_t* r, uint32_t addr) {
    asm volatile("ldmatrix.sync.aligned.m8n8.x4.trans.shared.b16 {%0,%1,%2,%3}, [%4];"
                 : "=r"(r[0]), "=r"(r[1]), "=r"(r[2]), "=r"(r[3]) : "r"(addr));
}
__device__ __forceinline__ void mma_bf16(float* c, const uint32_t* a, const uint32_t* b) {
    asm volatile(
        "mma.sync.aligned.m16n8k16.row.col.f32.bf16.bf16.f32 "
        "{%0,%1,%2,%3}, {%4,%5,%6,%7}, {%8,%9}, {%0,%1,%2,%3};"
        : "+f"(c[0]), "+f"(c[1]), "+f"(c[2]), "+f"(c[3])
        : "r"(a[0]), "r"(a[1]), "r"(a[2]), "r"(a[3]), "r"(b[0]), "r"(b[1]));
}
__device__ __forceinline__ uint32_t pack_bf(float e0, float e1) {
    uint32_t r;
    asm("cvt.rn.bf16x2.f32 %0, %1, %2;" : "=r"(r) : "f"(e1), "f"(e0));
    return r;
}
__device__ __forceinline__ float bfres(float x) {
    return x - __bfloat162float(__float2bfloat16(x));
}
__device__ __forceinline__ void cp16(uint32_t dst, const void* src) {
    asm volatile("cp.async.cg.shared.global [%0], [%1], 16;"
                 :: "r"(dst), "l"(src) : "memory");
}
#define CP_COMMIT() asm volatile("cp.async.commit_group;" ::: "memory")
#define CP_WAIT(n)  asm volatile("cp.async.wait_group %0;" :: "n"(n) : "memory")

// ============================================================================
// pre-pass: fp32 -> bf16 hi/lo planes
// ============================================================================
__global__ __launch_bounds__(256) void conv_kernel(const float* __restrict__ msa,
                                                   const float* __restrict__ Wq,
                                                   const float* __restrict__ Wk,
                                                   const float* __restrict__ Wv,
                                                   const float* __restrict__ Wo) {
    const int total = NP_A + 4 * NP_W;
    for (int i = blockIdx.x * 256 + threadIdx.x; i < total; i += gridDim.x * 256) {
        float2 v;
        uint32_t* hi;
        uint32_t* lo;
        int o;
        if (i < NP_A) {
            v = reinterpret_cast<const float2*>(msa)[i];
            hi = g_ahi; lo = g_alo; o = i;
        } else {
            int w = i - NP_A;
            const int m = w >> 15, off = w & (NP_W - 1);
            const float* W = (m == 0) ? Wq : (m == 1) ? Wk : (m == 2) ? Wv : Wo;
            v = reinterpret_cast<const float2*>(W)[off];
            hi = g_whi; lo = g_wlo; o = w;
        }
        hi[o] = pack_bf(v.x, v.y);
        lo[o] = pack_bf(bfres(v.x), bfres(v.y));
    }
}

// ============================================================================
// bf16 GEMM, tile 128(M) x 64(N), K-chunk = 32 halves, 80B rows, double-buf.
// Stage: A 2x10240 + B 2x5120 = 30720 B; x2 = 61440 B -> 3 CTAs/SM (RF-capped).
// ============================================================================
#define ROWSTRIDE 80
#define A_PLANE   (128 * ROWSTRIDE)     // 10240
#define B_PLANE   (64 * ROWSTRIDE)      // 5120
#define P_A_HI    0
#define P_A_LO    A_PLANE
#define P_B_HI    (2 * A_PLANE)
#define P_B_LO    (2 * A_PLANE + B_PLANE)
#define STAGE_SZ  (2 * A_PLANE + 2 * B_PLANE)   // 30720
#define GEMM_SMEM (2 * STAGE_SZ)                // 61440

__device__ __forceinline__ uint32_t a_addr(uint32_t base, int lane, int m_start, int k0,
                                           int stride) {
    const int tt = lane >> 3, ri = lane & 7;
    const int row = m_start + (tt & 1) * 8 + ri;
    const int kb  = k0 + (tt >> 1) * 8;
    return base + (uint32_t)(row * stride + kb * 2);
}
__device__ __forceinline__ uint32_t b_addr(uint32_t base, int lane, int n_start, int k0,
                                           int stride) {
    const int tt = lane >> 3, ri = lane & 7;
    const int row = n_start + (tt >> 1) * 8 + ri;
    const int kb  = k0 + (tt & 1) * 8;
    return base + (uint32_t)(row * stride + kb * 2);
}

// stage one K=32 chunk (A: 128 rows, B: 64 rows; per row per plane = 16 u32)
__device__ __forceinline__ void stage_chunk(uint32_t sbuf,
                                            const uint32_t* __restrict__ Ahi,
                                            const uint32_t* __restrict__ Alo,
                                            const uint32_t* __restrict__ Whi,
                                            const uint32_t* __restrict__ Wlo,
                                            int row0, int ncol0, int k0u, int tid) {
    // A: 2 threads/row, 32B (2 cp16) each per plane
    {
        const int row  = tid >> 1;
        const int half = tid & 1;
        const uint32_t drow = sbuf + (uint32_t)(row * ROWSTRIDE + half * 32);
        const uint32_t* a_hi = Ahi + (size_t)(row0 + row) * 128 + k0u + half * 8;
        const uint32_t* a_lo = Alo + (size_t)(row0 + row) * 128 + k0u + half * 8;
        #pragma unroll
        for (int j = 0; j < 2; j++) {
            cp16(drow + P_A_HI + j * 16, a_hi + j * 4);
            cp16(drow + P_A_LO + j * 16, a_lo + j * 4);
        }
    }
    // B: 4 threads/row, 16B (1 cp16) each per plane
    {
        const int row = tid >> 2;
        const int q   = tid & 3;
        const uint32_t drow = sbuf + (uint32_t)(row * ROWSTRIDE + q * 16);
        const uint32_t* w_hi = Whi + (size_t)(ncol0 + row) * 128 + k0u + q * 4;
        const uint32_t* w_lo = Wlo + (size_t)(ncol0 + row) * 128 + k0u + q * 4;
        cp16(drow + P_B_HI, w_hi);
        cp16(drow + P_B_LO, w_lo);
    }
}

__device__ __forceinline__ void gemm_body(const uint32_t* __restrict__ Ahi,
                                          const uint32_t* __restrict__ Alo,
                                          const uint32_t* __restrict__ Whi,
                                          const uint32_t* __restrict__ Wlo,
                                          char* smem, int row0, int ncol0,
                                          int tid, float acc[2][4][4]) {
    const int wid = tid >> 5, lane = tid & 31;
    const int wm = (wid & 3) * 32;       // 4 warps over M=128
    const int wn = (wid >> 2) * 32;      // 2 warps over N=64
    const uint32_t sb = smem_u32(smem);

    stage_chunk(sb, Ahi, Alo, Whi, Wlo, row0, ncol0, 0, tid);
    CP_COMMIT();

    for (int chunk = 0; chunk < 8; chunk++) {      // 8 chunks of K=32
        if (chunk < 7) {
            stage_chunk(sb + ((chunk + 1) & 1) * STAGE_SZ, Ahi, Alo, Whi, Wlo,
                        row0, ncol0, (chunk + 1) * 16, tid);
            CP_COMMIT();
            CP_WAIT(1);
        } else {
            CP_WAIT(0);
        }
        __syncthreads();

        const uint32_t base = sb + (chunk & 1) * STAGE_SZ;
        #pragma unroll
        for (int ks = 0; ks < 2; ks++) {
            const int k0 = ks * 16;
            uint32_t ah[2][4], al[2][4];
            #pragma unroll
            for (int mt = 0; mt < 2; mt++) {
                ldm_x4(ah[mt], a_addr(base + P_A_HI, lane, wm + mt * 16, k0, ROWSTRIDE));
                ldm_x4(al[mt], a_addr(base + P_A_LO, lane, wm + mt * 16, k0, ROWSTRIDE));
            }
            #pragma unroll
            for (int p = 0; p < 2; p++) {
                uint32_t bh[4], bl[4];
                ldm_x4(bh, b_addr(base + P_B_HI, lane, wn + p * 16, k0, ROWSTRIDE));
                ldm_x4(bl, b_addr(base + P_B_LO, lane, wn + p * 16, k0, ROWSTRIDE));
                #pragma unroll
                for (int mt = 0; mt < 2; mt++) {
                    #pragma unroll
                    for (int s = 0; s < 2; s++) {
                        float* c = acc[mt][p * 2 + s];
                        mma_bf16(c, ah[mt], bh + s * 2);
                        mma_bf16(c, ah[mt], bl + s * 2);
                        mma_bf16(c, al[mt], bh + s * 2);
                    }
                }
            }
        }
        __syncthreads();
    }
}

// ---------------------------------------------------------------------------
// QKV projection: grid (384 M-tiles, 4 N-tiles of 64, 3 matrices)
// ---------------------------------------------------------------------------
__global__ __launch_bounds__(256, 3) void qkv_tc() {
    extern __shared__ char smem[];
    const int tid   = threadIdx.x;
    const int row0  = blockIdx.x * 128;
    const int ncol0 = blockIdx.y * 64;
    const int z     = blockIdx.z;

    float acc[2][4][4];
    #pragma unroll
    for (int mt = 0; mt < 2; mt++)
        #pragma unroll
        for (int nt = 0; nt < 4; nt++)
            #pragma unroll
            for (int i = 0; i < 4; i++) acc[mt][nt][i] = 0.f;

    gemm_body(g_ahi, g_alo, g_whi + (size_t)z * NP_W, g_wlo + (size_t)z * NP_W,
              smem, row0, ncol0, tid, acc);

    const int wid = tid >> 5, lane = tid & 31;
    const int wm = (wid & 3) * 32, wn = (wid >> 2) * 32;
    const int g = lane >> 2, tig = lane & 3;

    #pragma unroll
    for (int mt = 0; mt < 2; mt++) {
        const int n1 = row0 + wm + mt * 16 + g;   // rows n1, n1+8 share s
        const int s1 = n1 / LL, l1 = n1 % LL;
        #pragma unroll
        for (int nt = 0; nt < 4; nt++) {
            const int j = ncol0 + wn + nt * 8 + 2 * tig;
            const int h = j >> 5, d = j & 31;
            const float* a = acc[mt][nt];
            const size_t i0 = ((((size_t)s1 * HH + h) * LL + l1) * HD + d) >> 1;
            const size_t i1 = i0 + 4 * HD;
            if (z == 0) {
                g_qb[i0] = pack_bf(a[0] * SCALE, a[1] * SCALE);
                g_qb[i1] = pack_bf(a[2] * SCALE, a[3] * SCALE);
            } else if (z == 1) {
                g_kb[i0] = pack_bf(a[0], a[1]);
                g_kb[i1] = pack_bf(a[2], a[3]);
            } else {
                g_vh[i0] = pack_bf(a[0], a[1]);
                g_vh[i1] = pack_bf(a[2], a[3]);
                g_vl[i0] = pack_bf(bfres(a[0]), bfres(a[1]));
                g_vl[i1] = pack_bf(bfres(a[2]), bfres(a[3]));
            }
        }
    }
}

// ---------------------------------------------------------------------------
// Output projection
// ---------------------------------------------------------------------------
__global__ __launch_bounds__(256, 3) void out_tc(float* __restrict__ C) {
    extern __shared__ char smem[];
    const int tid   = threadIdx.x;
    const int row0  = blockIdx.x * 128;
    const int ncol0 = blockIdx.y * 64;

    float acc[2][4][4];
    #pragma unroll
    for (int mt = 0; mt < 2; mt++)
        #pragma unroll
        for (int nt = 0; nt < 4; nt++)
            #pragma unroll
            for (int i = 0; i < 4; i++) acc[mt][nt][i] = 0.f;

    gemm_body(g_oh, g_ol, g_whi + (size_t)3 * NP_W, g_wlo + (size_t)3 * NP_W,
              smem, row0, ncol0, tid, acc);

    const int wid = tid >> 5, lane = tid & 31;
    const int wm = (wid & 3) * 32, wn = (wid >> 2) * 32;
    const int g = lane >> 2, tig = lane & 3;

    #pragma unroll
    for (int mt = 0; mt < 2; mt++) {
        const int n1 = row0 + wm + mt * 16 + g;
        #pragma unroll
        for (int nt = 0; nt < 4; nt++) {
            const int j = ncol0 + wn + nt * 8 + 2 * tig;
            *reinterpret_cast<float2*>(&C[(size_t)n1 * DD + j]) =
                make_float2(acc[mt][nt][0], acc[mt][nt][1]);
            *reinterpret_cast<float2*>(&C[(size_t)(n1 + 8) * DD + j]) =
                make_float2(acc[mt][nt][2], acc[mt][nt][3]);
        }
    }
}

// ============================================================================
// HMMA attention — unchanged from R13 (2 CTAs/SM).
// ============================================================================
#define AST_B 80
#define ATT_PLANE (LL * AST_B)
#define ATT_SMEM  (3 * ATT_PLANE)       // 92160

__device__ __forceinline__ uint32_t vt_addr(uint32_t base, int lane, int k0, int d0) {
    const int row = k0 + (lane & 7) + 8 * ((lane >> 3) & 1);
    const int col = d0 + 8 * (lane >> 4);
    return base + (uint32_t)(row * AST_B + col * 2);
}

__global__ __launch_bounds__(384, 2) void attn_tc() {
    extern __shared__ char sm[];
    const int sh  = blockIdx.x;
    const int tid = threadIdx.x, wid = tid >> 5, lane = tid & 31;
    const int g = lane >> 2, tig = lane & 3;
    const uint32_t sb   = smem_u32(sm);
    const uint32_t sbQK = sb;
    const uint32_t sbVh = sb + ATT_PLANE;
    const uint32_t sbVl = sb + 2 * ATT_PLANE;

    const size_t base32 = (size_t)sh * (LL * HD / 2);
    const uint4* Qg  = reinterpret_cast<const uint4*>(g_qb + base32);
    const uint4* Kg  = reinterpret_cast<const uint4*>(g_kb + base32);
    const uint4* Vhg = reinterpret_cast<const uint4*>(g_vh + base32);
    const uint4* Vlg = reinterpret_cast<const uint4*>(g_vl + base32);

    #pragma unroll
    for (int i = 0; i < 4; i++) {
        int idx = tid + 384 * i;
        int row = idx >> 2, part = idx & 3;
        *reinterpret_cast<uint4*>(sm + row * AST_B + part * 16) = Qg[idx];
    }
    __syncthreads();

    uint32_t qf[2][2][4];
    const int m0 = wid * 32;
    #pragma unroll
    for (int mt = 0; mt < 2; mt++)
        #pragma unroll
        for (int ks = 0; ks < 2; ks++)
            ldm_x4(qf[mt][ks], a_addr(sbQK, lane, m0 + mt * 16, ks * 16, AST_B));
    __syncthreads();

    #pragma unroll
    for (int i = 0; i < 4; i++) {
        int idx = tid + 384 * i;
        int row = idx >> 2, part = idx & 3;
        *reinterpret_cast<uint4*>(sm + row * AST_B + part * 16) = Kg[idx];
        *reinterpret_cast<uint4*>(sm + ATT_PLANE + row * AST_B + part * 16) = Vhg[idx];
        *reinterpret_cast<uint4*>(sm + 2 * ATT_PLANE + row * AST_B + part * 16) = Vlg[idx];
    }
    __syncthreads();

    float oacc[2][4][4];
    #pragma unroll
    for (int mt = 0; mt < 2; mt++)
        #pragma unroll
        for (int dt = 0; dt < 4; dt++)
            #pragma unroll
            for (int e = 0; e < 4; e++) oacc[mt][dt][e] = 0.f;
    float rs[2][2] = {{0.f, 0.f}, {0.f, 0.f}};

    for (int kc = 0; kc < LL / 16; kc++) {
        const int k0 = kc * 16;

        uint32_t kf[2][4];
        ldm_x4(kf[0], b_addr(sbQK, lane, k0, 0,  AST_B));
        ldm_x4(kf[1], b_addr(sbQK, lane, k0, 16, AST_B));

        float sacc[2][2][4];
        #pragma unroll
        for (int mt = 0; mt < 2; mt++)
            #pragma unroll
            for (int s = 0; s < 2; s++)
                #pragma unroll
                for (int e = 0; e < 4; e++) sacc[mt][s][e] = 0.f;

        #pragma unroll
        for (int mt = 0; mt < 2; mt++)
            #pragma unroll
            for (int ks = 0; ks < 2; ks++)
                #pragma unroll
                for (int s = 0; s < 2; s++)
                    mma_bf16(sacc[mt][s], qf[mt][ks], kf[ks] + 2 * s);

        uint32_t vh[2][4], vl[2][4];
        #pragma unroll
        for (int dg = 0; dg < 2; dg++) {
            ldm_x4_t(vh[dg], vt_addr(sbVh, lane, k0, dg * 16));
            ldm_x4_t(vl[dg], vt_addr(sbVl, lane, k0, dg * 16));
        }

        #pragma unroll
        for (int mt = 0; mt < 2; mt++) {
            float p[2][4];
            #pragma unroll
            for (int s = 0; s < 2; s++)
                #pragma unroll
                for (int e = 0; e < 4; e++) p[s][e] = __expf(sacc[mt][s][e]);
            rs[mt][0] += p[0][0] + p[0][1] + p[1][0] + p[1][1];
            rs[mt][1] += p[0][2] + p[0][3] + p[1][2] + p[1][3];

            uint32_t ahi[4], alo[4];
            ahi[0] = pack_bf(p[0][0], p[0][1]);
            ahi[1] = pack_bf(p[0][2], p[0][3]);
            ahi[2] = pack_bf(p[1][0], p[1][1]);
            ahi[3] = pack_bf(p[1][2], p[1][3]);
            alo[0] = pack_bf(bfres(p[0][0]), bfres(p[0][1]));
            alo[1] = pack_bf(bfres(p[0][2]), bfres(p[0][3]));
            alo[2] = pack_bf(bfres(p[1][0]), bfres(p[1][1]));
            alo[3] = pack_bf(bfres(p[1][2]), bfres(p[1][3]));

            #pragma unroll
            for (int dg = 0; dg < 2; dg++)
                #pragma unroll
                for (int s = 0; s < 2; s++) {
                    float* c = oacc[mt][dg * 2 + s];
                    mma_bf16(c, ahi, vh[dg] + 2 * s);
                    mma_bf16(c, ahi, vl[dg] + 2 * s);
                    mma_bf16(c, alo, vh[dg] + 2 * s);
                }
        }
    }

    #pragma unroll
    for (int mt = 0; mt < 2; mt++)
        #pragma unroll
        for (int r = 0; r < 2; r++) {
            float v = rs[mt][r];
            v += __shfl_xor_sync(0xFFFFFFFFu, v, 1);
            v += __shfl_xor_sync(0xFFFFFFFFu, v, 2);
            rs[mt][r] = 1.f / v;
        }

    const int s_ = sh >> 3, h_ = sh & 7;
    #pragma unroll
    for (int mt = 0; mt < 2; mt++) {
        const int l = m0 + mt * 16 + g;
        const size_t rowbase = (((size_t)s_ * LL + l) * DD + h_ * HD) >> 1;
        #pragma unroll
        for (int dt = 0; dt < 4; dt++) {
            const int d = dt * 8 + 2 * tig;
            const float* c = oacc[mt][dt];
            float v0 = c[0] * rs[mt][0], v1 = c[1] * rs[mt][0];
            float v2 = c[2] * rs[mt][1], v3 = c[3] * rs[mt][1];
            const size_t i0 = rowbase + (d >> 1);
            const size_t i1 = i0 + 4 * DD;
            g_oh[i0] = pack_bf(v0, v1);
            g_ol[i0] = pack_bf(bfres(v0), bfres(v1));
            g_oh[i1] = pack_bf(v2, v3);
            g_ol[i1] = pack_bf(bfres(v2), bfres(v3));
        }
    }
}

// ---------------------------------------------------------------------------
extern "C" void kernel_launch(void* const* d_in, const int* in_sizes, int n_in,
                              void* d_out, int out_size) {
    (void)in_sizes; (void)n_in; (void)out_size;
    const float* msa = (const float*)d_in[0];
    // d_in[1] = pair, d_in[6] = Wpb: dead code in the reference
    const float* Wq = (const float*)d_in[2];
    const float* Wk = (const float*)d_in[3];
    const float* Wv = (const float*)d_in[4];
    const float* Wo = (const float*)d_in[5];
    float* out = (float*)d_out;

    cudaFuncSetAttribute(qkv_tc, cudaFuncAttributeMaxDynamicSharedMemorySize, GEMM_SMEM);
    cudaFuncSetAttribute(out_tc, cudaFuncAttributeMaxDynamicSharedMemorySize, GEMM_SMEM);
    cudaFuncSetAttribute(attn_tc, cudaFuncAttributeMaxDynamicSharedMemorySize, ATT_SMEM);

    conv_kernel<<<4096, 256>>>(msa, Wq, Wk, Wv, Wo);

    dim3 gq(NROWS / 128, 4, 3);
    qkv_tc<<<gq, 256, GEMM_SMEM>>>();

    attn_tc<<<SS * HH, 384, ATT_SMEM>>>();

    dim3 go(NROWS / 128, 4, 1);
    out_tc<<<go, 256, GEMM_SMEM>>>(out);
}